// round 6
// baseline (speedup 1.0000x reference)
#include <cuda_runtime.h>
#include <cuda_bf16.h>
#include <math.h>
#include <stdint.h>

#define BATCH 4
#define SEQ   4096
#define DIM   1024
#define HDIM  64

__device__ float g_QKV[3][(size_t)BATCH * SEQ * HDIM];

// ===================== helpers =====================
__device__ __forceinline__ uint32_t smem_u32(const void* p) {
    uint32_t a;
    asm("{ .reg .u64 t; cvta.to.shared.u64 t, %1; cvt.u32.u64 %0, t; }" : "=r"(a) : "l"(p));
    return a;
}
__device__ __forceinline__ float ex2(float x) {
    float y; asm("ex2.approx.f32 %0, %1;" : "=f"(y) : "f"(x)); return y;
}
__device__ __forceinline__ void cvt_pair(float a, float b, uint32_t& hi, uint32_t& lo) {
    __nv_bfloat16 ah = __float2bfloat16(a);
    __nv_bfloat16 bh = __float2bfloat16(b);
    float ar = a - __bfloat162float(ah);
    float br = b - __bfloat162float(bh);
    __nv_bfloat162 H = __halves2bfloat162(ah, bh);
    __nv_bfloat162 L = __halves2bfloat162(__float2bfloat16(ar), __float2bfloat16(br));
    hi = *reinterpret_cast<uint32_t*>(&H);
    lo = *reinterpret_cast<uint32_t*>(&L);
}

#define LDSM_X4(r0, r1, r2, r3, addr) \
    asm volatile("ldmatrix.sync.aligned.m8n8.x4.shared.b16 {%0,%1,%2,%3}, [%4];" \
        : "=r"(r0), "=r"(r1), "=r"(r2), "=r"(r3) : "r"(addr))
#define LDSM_X2(r0, r1, addr) \
    asm volatile("ldmatrix.sync.aligned.m8n8.x2.shared.b16 {%0,%1}, [%2];" \
        : "=r"(r0), "=r"(r1) : "r"(addr))
#define MMA16816(d, a, b) \
    asm volatile("mma.sync.aligned.m16n8k16.row.col.f32.bf16.bf16.f32 " \
        "{%0,%1,%2,%3}, {%4,%5,%6,%7}, {%8,%9}, {%0,%1,%2,%3};" \
        : "+f"((d)[0]), "+f"((d)[1]), "+f"((d)[2]), "+f"((d)[3]) \
        : "r"((a)[0]), "r"((a)[1]), "r"((a)[2]), "r"((a)[3]), "r"((b)[0]), "r"((b)[1]))
#define BAR_GRP(id) asm volatile("bar.sync %0, 128;" :: "r"(id) : "memory")

// ---------------------------------------------------------------------------
// QKV via tensor cores. Fused N=192 (wq|wk|wv), M-tile 128, K-chunk 16.
// bf16 hi/lo 3-term. 256 threads = 8 warps x 16 rows. grid = 128.
// smem tiles stride 24 bf16 (48 B): 16B-aligned, conflict-free ldmatrix.
// ---------------------------------------------------------------------------
#define XSTR 24
#define QKV_SM (128*XSTR*2*2 + 192*XSTR*2*2)   // XH+XL + WH+WL = 30720
__global__ __launch_bounds__(256, 1) void qkv_kernel(
    const float* __restrict__ x, const float* __restrict__ wq,
    const float* __restrict__ wk, const float* __restrict__ wv)
{
    __shared__ __align__(16) __nv_bfloat16 XH[128 * XSTR], XL[128 * XSTR];
    __shared__ __align__(16) __nv_bfloat16 WH[192 * XSTR], WL[192 * XSTR];

    const int tid = threadIdx.x;
    const int w = tid >> 5, l = tid & 31;
    const int m0 = blockIdx.x * 128;
    const float* Wp[3] = {wq, wk, wv};

    float acc[24][4];
    #pragma unroll
    for (int j = 0; j < 24; j++) { acc[j][0] = acc[j][1] = acc[j][2] = acc[j][3] = 0.0f; }

    for (int it = 0; it < DIM / 16; it++) {
        const int k0 = it * 16;
        // X chunk: 128 rows x 16 k
        {
            int r = tid >> 1, c = (tid & 1) * 8;
            const float* xp = x + (size_t)(m0 + r) * DIM + k0 + c;
            float4 v0 = *(const float4*)(xp);
            float4 v1 = *(const float4*)(xp + 4);
            uint32_t h, lo;
            uint32_t base = (uint32_t)r * XSTR + c;
            cvt_pair(v0.x, v0.y, h, lo);
            *(uint32_t*)(XH + base)     = h;  *(uint32_t*)(XL + base)     = lo;
            cvt_pair(v0.z, v0.w, h, lo);
            *(uint32_t*)(XH + base + 2) = h;  *(uint32_t*)(XL + base + 2) = lo;
            cvt_pair(v1.x, v1.y, h, lo);
            *(uint32_t*)(XH + base + 4) = h;  *(uint32_t*)(XL + base + 4) = lo;
            cvt_pair(v1.z, v1.w, h, lo);
            *(uint32_t*)(XH + base + 6) = h;  *(uint32_t*)(XL + base + 6) = lo;
        }
        // W chunk: 192 rows x 16 k (3 passes of 64 rows)
        #pragma unroll
        for (int p = 0; p < 3; p++) {
            int n = p * 64 + (tid >> 2), c = (tid & 3) * 4;
            const float* wp = Wp[p] + (size_t)(n - p * 64) * DIM + k0 + c;
            float4 v = *(const float4*)(wp);
            uint32_t h, lo;
            uint32_t base = (uint32_t)n * XSTR + c;
            cvt_pair(v.x, v.y, h, lo);
            *(uint32_t*)(WH + base)     = h;  *(uint32_t*)(WL + base)     = lo;
            cvt_pair(v.z, v.w, h, lo);
            *(uint32_t*)(WH + base + 2) = h;  *(uint32_t*)(WL + base + 2) = lo;
        }
        __syncthreads();

        uint32_t ah[4], al[4];
        uint32_t arow = ((uint32_t)(16 * w + (l & 15)) * XSTR + (uint32_t)((l >> 4) * 8)) * 2;
        LDSM_X4(ah[0], ah[1], ah[2], ah[3], smem_u32((const char*)XH + arow));
        LDSM_X4(al[0], al[1], al[2], al[3], smem_u32((const char*)XL + arow));
        #pragma unroll
        for (int j = 0; j < 24; j++) {
            uint32_t brow = ((uint32_t)(8 * j + (l & 7)) * XSTR + (uint32_t)(((l >> 3) & 1) * 8)) * 2;
            uint32_t bh[2], bl[2];
            LDSM_X2(bh[0], bh[1], smem_u32((const char*)WH + brow));
            LDSM_X2(bl[0], bl[1], smem_u32((const char*)WL + brow));
            MMA16816(acc[j], ah, bh);
            MMA16816(acc[j], ah, bl);
            MMA16816(acc[j], al, bh);
        }
        __syncthreads();
    }

    // epilogue: D rows r0 = 16w + l/4, r1 = r0+8; cols 8j + 2(l&3)
    {
        int r0 = m0 + 16 * w + (l >> 2);
        int col2 = 2 * (l & 3);
        #pragma unroll
        for (int j = 0; j < 24; j++) {
            int mat = j >> 3;
            int col = 8 * (j & 7) + col2;
            float* o0 = g_QKV[mat] + (size_t)r0 * HDIM + col;
            float2 v0 = {acc[j][0], acc[j][1]};
            float2 v1 = {acc[j][2], acc[j][3]};
            *(float2*)o0 = v0;
            *(float2*)(o0 + 8 * HDIM) = v1;
        }
    }
}

// ---------------------------------------------------------------------------
// FA2 attention, mma.sync bf16 hi/lo 3-term, 2 independent groups of 4 warps.
// Group g owns q rows [64g, 64g+64), iterates ALL KV tiles on its own named
// barrier with private K/V smem buffers -> groups de-phase, pipes overlap.
// grid = (SEQ/128, BATCH).
// ---------------------------------------------------------------------------
#define RSTR    144
#define GKH     0
#define GKL     9216
#define GVH     18432
#define GVL     27648
#define GRP_BYTES 36864
#define ATTN_SM  (2 * GRP_BYTES)

__global__ __launch_bounds__(256, 1) void attn_kernel(float* __restrict__ out)
{
    extern __shared__ __align__(16) char smraw[];

    const int tid = threadIdx.x;
    const int w = tid >> 5, l = tid & 31;
    const int g = w >> 2, wg = w & 3;
    const int t = tid & 127;                    // thread id within group
    const int b = blockIdx.y;
    const int q0 = blockIdx.x * 128;

    char* sm = smraw + g * GRP_BYTES;

    const float* Qg = g_QKV[0] + (size_t)b * SEQ * HDIM;
    const float* Kg = g_QKV[1] + (size_t)b * SEQ * HDIM;
    const float* Vg = g_QKV[2] + (size_t)b * SEQ * HDIM;

    const float SCALE = 0.125f * 1.4426950408889634f;   // fold log2(e): use ex2

    // ---- stage Q (64 rows of this group) into KH (hi) / VH (lo)
    {
        int r = t >> 1, c0 = (t & 1) * 32;
        const float* qr = Qg + (size_t)(q0 + 64 * g + r) * HDIM + c0;
        #pragma unroll
        for (int q = 0; q < 8; q++) {
            float4 v = *(const float4*)(qr + q * 4);
            uint32_t h0, l0w, h1, l1w;
            cvt_pair(v.x * SCALE, v.y * SCALE, h0, l0w);
            cvt_pair(v.z * SCALE, v.w * SCALE, h1, l1w);
            uint32_t off = (uint32_t)r * RSTR + (uint32_t)(c0 + q * 4) * 2;
            *(uint32_t*)(sm + GKH + off)     = h0;
            *(uint32_t*)(sm + GKH + off + 4) = h1;
            *(uint32_t*)(sm + GVH + off)     = l0w;
            *(uint32_t*)(sm + GVH + off + 4) = l1w;
        }
    }
    BAR_GRP(g + 1);

    uint32_t qh[4][4], ql[4][4];
    {
        uint32_t rowb = (uint32_t)(16 * wg + (l & 15)) * RSTR + (uint32_t)((l >> 4) * 8) * 2;
        #pragma unroll
        for (int kk = 0; kk < 4; kk++) {
            LDSM_X4(qh[kk][0], qh[kk][1], qh[kk][2], qh[kk][3], smem_u32(sm + GKH + rowb + kk * 32));
            LDSM_X4(ql[kk][0], ql[kk][1], ql[kk][2], ql[kk][3], smem_u32(sm + GVH + rowb + kk * 32));
        }
    }
    BAR_GRP(g + 1);

    float o[8][4];
    #pragma unroll
    for (int j = 0; j < 8; j++) { o[j][0] = o[j][1] = o[j][2] = o[j][3] = 0.0f; }
    float m0r = -1e30f, m1r = -1e30f, l0r = 0.0f, l1r = 0.0f;

    for (int it = 0; it < SEQ / 64; it++) {
        const int kt = it * 64;

        // ---- K tile -> [key][hd] hi/lo (group-private)
        {
            int r = t >> 1, c0 = (t & 1) * 32;
            const float* kr = Kg + (size_t)(kt + r) * HDIM + c0;
            #pragma unroll
            for (int q = 0; q < 8; q++) {
                float4 v = *(const float4*)(kr + q * 4);
                uint32_t h0, l0w, h1, l1w;
                cvt_pair(v.x, v.y, h0, l0w);
                cvt_pair(v.z, v.w, h1, l1w);
                uint32_t off = (uint32_t)r * RSTR + (uint32_t)(c0 + q * 4) * 2;
                *(uint32_t*)(sm + GKH + off)     = h0;
                *(uint32_t*)(sm + GKH + off + 4) = h1;
                *(uint32_t*)(sm + GKL + off)     = l0w;
                *(uint32_t*)(sm + GKL + off + 4) = l1w;
            }
        }
        // ---- V tile -> transposed [hd][key] hi/lo
        {
            int j0 = (t & 31) * 2, d0 = (t >> 5) * 16;
            const float* v0p = Vg + (size_t)(kt + j0) * HDIM + d0;
            const float* v1p = v0p + HDIM;
            float a0[16], a1[16];
            #pragma unroll
            for (int q = 0; q < 4; q++) {
                *(float4*)(a0 + q * 4) = *(const float4*)(v0p + q * 4);
                *(float4*)(a1 + q * 4) = *(const float4*)(v1p + q * 4);
            }
            #pragma unroll
            for (int d = 0; d < 16; d++) {
                uint32_t hi, lo;
                cvt_pair(a0[d], a1[d], hi, lo);
                uint32_t off = (uint32_t)(d0 + d) * RSTR + (uint32_t)j0 * 2;
                *(uint32_t*)(sm + GVH + off) = hi;
                *(uint32_t*)(sm + GVL + off) = lo;
            }
        }
        BAR_GRP(g + 1);

        // ---- S = Q @ K^T
        float s[8][4];
        #pragma unroll
        for (int j = 0; j < 8; j++) {
            s[j][0] = s[j][1] = s[j][2] = s[j][3] = 0.0f;
            uint32_t rowb = (uint32_t)(8 * j + (l & 7)) * RSTR + (uint32_t)(((l >> 3) & 1) * 8) * 2;
            #pragma unroll
            for (int kk = 0; kk < 4; kk++) {
                uint32_t bh[2], bl[2];
                LDSM_X2(bh[0], bh[1], smem_u32(sm + GKH + rowb + kk * 32));
                LDSM_X2(bl[0], bl[1], smem_u32(sm + GKL + rowb + kk * 32));
                MMA16816(s[j], qh[kk], bh);
                MMA16816(s[j], qh[kk], bl);
                MMA16816(s[j], ql[kk], bh);
            }
        }

        // ---- online softmax in log2 domain (ex2)
        float rm0 = m0r, rm1 = m1r;
        #pragma unroll
        for (int j = 0; j < 8; j++) {
            rm0 = fmaxf(rm0, fmaxf(s[j][0], s[j][1]));
            rm1 = fmaxf(rm1, fmaxf(s[j][2], s[j][3]));
        }
        rm0 = fmaxf(rm0, __shfl_xor_sync(0xffffffffu, rm0, 1));
        rm0 = fmaxf(rm0, __shfl_xor_sync(0xffffffffu, rm0, 2));
        rm1 = fmaxf(rm1, __shfl_xor_sync(0xffffffffu, rm1, 1));
        rm1 = fmaxf(rm1, __shfl_xor_sync(0xffffffffu, rm1, 2));
        float c0f = ex2(m0r - rm0), c1f = ex2(m1r - rm1);
        m0r = rm0;  m1r = rm1;
        float ls0 = 0.0f, ls1 = 0.0f;
        #pragma unroll
        for (int j = 0; j < 8; j++) {
            s[j][0] = ex2(s[j][0] - rm0);
            s[j][1] = ex2(s[j][1] - rm0);
            s[j][2] = ex2(s[j][2] - rm1);
            s[j][3] = ex2(s[j][3] - rm1);
            ls0 += s[j][0] + s[j][1];
            ls1 += s[j][2] + s[j][3];
            o[j][0] *= c0f;  o[j][1] *= c0f;
            o[j][2] *= c1f;  o[j][3] *= c1f;
        }
        ls0 += __shfl_xor_sync(0xffffffffu, ls0, 1);
        ls0 += __shfl_xor_sync(0xffffffffu, ls0, 2);
        ls1 += __shfl_xor_sync(0xffffffffu, ls1, 1);
        ls1 += __shfl_xor_sync(0xffffffffu, ls1, 2);
        l0r = l0r * c0f + ls0;
        l1r = l1r * c1f + ls1;

        // ---- O += P @ V
        #pragma unroll
        for (int kk = 0; kk < 4; kk++) {
            uint32_t ah[4], al[4];
            cvt_pair(s[2 * kk][0],     s[2 * kk][1],     ah[0], al[0]);
            cvt_pair(s[2 * kk][2],     s[2 * kk][3],     ah[1], al[1]);
            cvt_pair(s[2 * kk + 1][0], s[2 * kk + 1][1], ah[2], al[2]);
            cvt_pair(s[2 * kk + 1][2], s[2 * kk + 1][3], ah[3], al[3]);
            #pragma unroll
            for (int j = 0; j < 8; j++) {
                uint32_t rowb = (uint32_t)(8 * j + (l & 7)) * RSTR + (uint32_t)(kk * 16 + ((l >> 3) & 1) * 8) * 2;
                uint32_t vh[2], vl[2];
                LDSM_X2(vh[0], vh[1], smem_u32(sm + GVH + rowb));
                LDSM_X2(vl[0], vl[1], smem_u32(sm + GVL + rowb));
                MMA16816(o[j], ah, vh);
                MMA16816(o[j], ah, vl);
                MMA16816(o[j], al, vh);
            }
        }
        BAR_GRP(g + 1);
    }

    // ---- epilogue
    {
        float inv0 = 1.0f / l0r, inv1 = 1.0f / l1r;
        int r0 = q0 + 64 * g + 16 * wg + (l >> 2);
        int col = 2 * (l & 3);
        float* op0 = out + ((size_t)b * SEQ + r0) * HDIM;
        float* op1 = op0 + 8 * HDIM;
        #pragma unroll
        for (int j = 0; j < 8; j++) {
            float2 v0 = {o[j][0] * inv0, o[j][1] * inv0};
            float2 v1 = {o[j][2] * inv1, o[j][3] * inv1};
            *(float2*)(op0 + 8 * j + col) = v0;
            *(float2*)(op1 + 8 * j + col) = v1;
        }
    }
}

// ---------------------------------------------------------------------------
extern "C" void kernel_launch(void* const* d_in, const int* in_sizes, int n_in,
                              void* d_out, int out_size)
{
    const float* x  = (const float*)d_in[0];
    const float* wq = (const float*)d_in[1];
    const float* wk = (const float*)d_in[2];
    const float* wv = (const float*)d_in[3];
    float* out = (float*)d_out;

    qkv_kernel<<<(BATCH * SEQ) / 128, 256>>>(x, wq, wk, wv);

    cudaFuncSetAttribute(attn_kernel, cudaFuncAttributeMaxDynamicSharedMemorySize, ATTN_SM);
    attn_kernel<<<dim3(SEQ / 128, BATCH), 256, ATTN_SM>>>(out);
}

// round 8
// speedup vs baseline: 1.3139x; 1.3139x over previous
#include <cuda_runtime.h>
#include <cuda_bf16.h>
#include <math.h>
#include <stdint.h>

#define BATCH 4
#define SEQ   4096
#define DIM   1024
#define HDIM  64

__device__ float g_QKV[3][(size_t)BATCH * SEQ * HDIM];

// ===================== helpers =====================
__device__ __forceinline__ uint32_t smem_u32(const void* p) {
    uint32_t a;
    asm("{ .reg .u64 t; cvta.to.shared.u64 t, %1; cvt.u32.u64 %0, t; }" : "=r"(a) : "l"(p));
    return a;
}
__device__ __forceinline__ float ex2(float x) {
    float y; asm("ex2.approx.f32 %0, %1;" : "=f"(y) : "f"(x)); return y;
}
__device__ __forceinline__ void cvt_pair(float a, float b, uint32_t& hi, uint32_t& lo) {
    __nv_bfloat16 ah = __float2bfloat16(a);
    __nv_bfloat16 bh = __float2bfloat16(b);
    float ar = a - __bfloat162float(ah);
    float br = b - __bfloat162float(bh);
    __nv_bfloat162 H = __halves2bfloat162(ah, bh);
    __nv_bfloat162 L = __halves2bfloat162(__float2bfloat16(ar), __float2bfloat16(br));
    hi = *reinterpret_cast<uint32_t*>(&H);
    lo = *reinterpret_cast<uint32_t*>(&L);
}

#define LDSM_X4(r0, r1, r2, r3, addr) \
    asm volatile("ldmatrix.sync.aligned.m8n8.x4.shared.b16 {%0,%1,%2,%3}, [%4];" \
        : "=r"(r0), "=r"(r1), "=r"(r2), "=r"(r3) : "r"(addr))
#define LDSM_X2(r0, r1, addr) \
    asm volatile("ldmatrix.sync.aligned.m8n8.x2.shared.b16 {%0,%1}, [%2];" \
        : "=r"(r0), "=r"(r1) : "r"(addr))
#define MMA16816(d, a, b) \
    asm volatile("mma.sync.aligned.m16n8k16.row.col.f32.bf16.bf16.f32 " \
        "{%0,%1,%2,%3}, {%4,%5,%6,%7}, {%8,%9}, {%0,%1,%2,%3};" \
        : "+f"((d)[0]), "+f"((d)[1]), "+f"((d)[2]), "+f"((d)[3]) \
        : "r"((a)[0]), "r"((a)[1]), "r"((a)[2]), "r"((a)[3]), "r"((b)[0]), "r"((b)[1]))
#define CP16(dst, src) \
    asm volatile("cp.async.cg.shared.global [%0], [%1], 16;" :: "r"(dst), "l"(src) : "memory")
#define CP_COMMIT() asm volatile("cp.async.commit_group;" ::: "memory")
#define CP_WAIT0()  asm volatile("cp.async.wait_group 0;" ::: "memory")

// ---------------------------------------------------------------------------
// QKV via tensor cores (R6, measured ~96us). Fused N=192, M-tile 128, K-chunk 16.
// ---------------------------------------------------------------------------
#define XSTR 24
__global__ __launch_bounds__(256, 1) void qkv_kernel(
    const float* __restrict__ x, const float* __restrict__ wq,
    const float* __restrict__ wk, const float* __restrict__ wv)
{
    __shared__ __align__(16) __nv_bfloat16 XH[128 * XSTR], XL[128 * XSTR];
    __shared__ __align__(16) __nv_bfloat16 WH[192 * XSTR], WL[192 * XSTR];

    const int tid = threadIdx.x;
    const int w = tid >> 5, l = tid & 31;
    const int m0 = blockIdx.x * 128;
    const float* Wp[3] = {wq, wk, wv};

    float acc[24][4];
    #pragma unroll
    for (int j = 0; j < 24; j++) { acc[j][0] = acc[j][1] = acc[j][2] = acc[j][3] = 0.0f; }

    for (int it = 0; it < DIM / 16; it++) {
        const int k0 = it * 16;
        {
            int r = tid >> 1, c = (tid & 1) * 8;
            const float* xp = x + (size_t)(m0 + r) * DIM + k0 + c;
            float4 v0 = *(const float4*)(xp);
            float4 v1 = *(const float4*)(xp + 4);
            uint32_t h, lo;
            uint32_t base = (uint32_t)r * XSTR + c;
            cvt_pair(v0.x, v0.y, h, lo);
            *(uint32_t*)(XH + base)     = h;  *(uint32_t*)(XL + base)     = lo;
            cvt_pair(v0.z, v0.w, h, lo);
            *(uint32_t*)(XH + base + 2) = h;  *(uint32_t*)(XL + base + 2) = lo;
            cvt_pair(v1.x, v1.y, h, lo);
            *(uint32_t*)(XH + base + 4) = h;  *(uint32_t*)(XL + base + 4) = lo;
            cvt_pair(v1.z, v1.w, h, lo);
            *(uint32_t*)(XH + base + 6) = h;  *(uint32_t*)(XL + base + 6) = lo;
        }
        #pragma unroll
        for (int p = 0; p < 3; p++) {
            int n = p * 64 + (tid >> 2), c = (tid & 3) * 4;
            const float* wp = Wp[p] + (size_t)(n - p * 64) * DIM + k0 + c;
            float4 v = *(const float4*)(wp);
            uint32_t h, lo;
            uint32_t base = (uint32_t)n * XSTR + c;
            cvt_pair(v.x, v.y, h, lo);
            *(uint32_t*)(WH + base)     = h;  *(uint32_t*)(WL + base)     = lo;
            cvt_pair(v.z, v.w, h, lo);
            *(uint32_t*)(WH + base + 2) = h;  *(uint32_t*)(WL + base + 2) = lo;
        }
        __syncthreads();

        uint32_t ah[4], al[4];
        uint32_t arow = ((uint32_t)(16 * w + (l & 15)) * XSTR + (uint32_t)((l >> 4) * 8)) * 2;
        LDSM_X4(ah[0], ah[1], ah[2], ah[3], smem_u32((const char*)XH + arow));
        LDSM_X4(al[0], al[1], al[2], al[3], smem_u32((const char*)XL + arow));
        #pragma unroll
        for (int j = 0; j < 24; j++) {
            uint32_t brow = ((uint32_t)(8 * j + (l & 7)) * XSTR + (uint32_t)(((l >> 3) & 1) * 8)) * 2;
            uint32_t bh[2], bl[2];
            LDSM_X2(bh[0], bh[1], smem_u32((const char*)WH + brow));
            LDSM_X2(bl[0], bl[1], smem_u32((const char*)WL + brow));
            MMA16816(acc[j], ah, bh);
            MMA16816(acc[j], ah, bl);
            MMA16816(acc[j], al, bh);
        }
        __syncthreads();
    }
    {
        int r0 = m0 + 16 * w + (l >> 2);
        int col2 = 2 * (l & 3);
        #pragma unroll
        for (int j = 0; j < 24; j++) {
            int mat = j >> 3;
            int col = 8 * (j & 7) + col2;
            float* o0 = g_QKV[mat] + (size_t)r0 * HDIM + col;
            float2 v0 = {acc[j][0], acc[j][1]};
            float2 v1 = {acc[j][2], acc[j][3]};
            *(float2*)o0 = v0;
            *(float2*)(o0 + 8 * HDIM) = v1;
        }
    }
}

// ---------------------------------------------------------------------------
// FA2 attention (R5 structure) + cp.async double-buffered fp32 staging + ex2.
// 256 threads = 8 warps x 16 q-rows, KV tile 64. grid = (SEQ/128, BATCH).
// ---------------------------------------------------------------------------
#define RSTR    144
#define KH_OFF  0
#define KL_OFF  9216
#define VH_OFF  18432
#define VL_OFF  27648
#define SSTG    68                            // stage stride in floats
#define STG_BYTES (64 * SSTG * 4)             // 17408 per K or V tile
#define STG0    36864
#define ATTN_SM (STG0 + 4 * STG_BYTES)        // 106496

__global__ __launch_bounds__(256, 1) void attn_kernel(float* __restrict__ out)
{
    extern __shared__ __align__(16) char sm[];

    const int tid = threadIdx.x;
    const int w = tid >> 5, l = tid & 31;
    const int b = blockIdx.y;
    const int q0 = blockIdx.x * 128;

    const float* Qg = g_QKV[0] + (size_t)b * SEQ * HDIM;
    const float* Kg = g_QKV[1] + (size_t)b * SEQ * HDIM;
    const float* Vg = g_QKV[2] + (size_t)b * SEQ * HDIM;

    const float SCALE = 0.125f * 1.4426950408889634f;   // fold log2(e) -> ex2 softmax

    // ---- prologue: async-stage tile 0, and build Q fragments meanwhile
    {
        #pragma unroll
        for (int p = 0; p < 4; p++) {
            int chunk = tid + p * 256;
            int r = chunk >> 4, c4 = (chunk & 15) * 4;
            uint32_t dk = smem_u32(sm + STG0 + (uint32_t)(r * SSTG + c4) * 4);
            uint32_t dv = smem_u32(sm + STG0 + STG_BYTES + (uint32_t)(r * SSTG + c4) * 4);
            CP16(dk, Kg + (size_t)r * HDIM + c4);
            CP16(dv, Vg + (size_t)r * HDIM + c4);
        }
        CP_COMMIT();
    }
    // Q tile -> smem (hi in KH area, lo in VH area), scaled
    {
        int r = tid >> 1, c0 = (tid & 1) * 32;
        const float* qr = Qg + (size_t)(q0 + r) * HDIM + c0;
        #pragma unroll
        for (int q = 0; q < 8; q++) {
            float4 v = *(const float4*)(qr + q * 4);
            uint32_t h0, l0w, h1, l1w;
            cvt_pair(v.x * SCALE, v.y * SCALE, h0, l0w);
            cvt_pair(v.z * SCALE, v.w * SCALE, h1, l1w);
            uint32_t off = (uint32_t)r * RSTR + (uint32_t)(c0 + q * 4) * 2;
            *(uint32_t*)(sm + KH_OFF + off)     = h0;
            *(uint32_t*)(sm + KH_OFF + off + 4) = h1;
            *(uint32_t*)(sm + VH_OFF + off)     = l0w;
            *(uint32_t*)(sm + VH_OFF + off + 4) = l1w;
        }
    }
    __syncthreads();

    uint32_t qh[4][4], ql[4][4];
    {
        uint32_t rowb = (uint32_t)(16 * w + (l & 15)) * RSTR + (uint32_t)((l >> 4) * 8) * 2;
        #pragma unroll
        for (int kk = 0; kk < 4; kk++) {
            LDSM_X4(qh[kk][0], qh[kk][1], qh[kk][2], qh[kk][3], smem_u32(sm + KH_OFF + rowb + kk * 32));
            LDSM_X4(ql[kk][0], ql[kk][1], ql[kk][2], ql[kk][3], smem_u32(sm + VH_OFF + rowb + kk * 32));
        }
    }

    float o[8][4];
    #pragma unroll
    for (int j = 0; j < 8; j++) { o[j][0] = o[j][1] = o[j][2] = o[j][3] = 0.0f; }
    float m0r = -1e30f, m1r = -1e30f, l0r = 0.0f, l1r = 0.0f;

    for (int it = 0; it < SEQ / 64; it++) {
        const char* stgK = sm + STG0 + (it & 1) * 2 * STG_BYTES;
        const char* stgV = stgK + STG_BYTES;

        __syncthreads();   // prev compute done reading bf16 bufs (iter0: Q frags done)
        CP_WAIT0();        // stage[cur] landed

        // ---- convert K stage -> [key][hd] hi/lo bf16
        {
            int r = tid >> 2, c0 = (tid & 3) * 16;
            const float* kr = (const float*)stgK + r * SSTG + c0;
            #pragma unroll
            for (int q = 0; q < 4; q++) {
                float4 v = *(const float4*)(kr + q * 4);
                uint32_t h0, l0w, h1, l1w;
                cvt_pair(v.x, v.y, h0, l0w);
                cvt_pair(v.z, v.w, h1, l1w);
                uint32_t off = (uint32_t)r * RSTR + (uint32_t)(c0 + q * 4) * 2;
                *(uint32_t*)(sm + KH_OFF + off)     = h0;
                *(uint32_t*)(sm + KH_OFF + off + 4) = h1;
                *(uint32_t*)(sm + KL_OFF + off)     = l0w;
                *(uint32_t*)(sm + KL_OFF + off + 4) = l1w;
            }
        }
        // ---- convert V stage -> transposed [hd][key] hi/lo bf16
        {
            int j0 = (tid & 31) * 2, d0 = (tid >> 5) * 8;
            const float* v0p = (const float*)stgV + j0 * SSTG + d0;
            const float* v1p = v0p + SSTG;
            float a0[8], a1[8];
            *(float4*)(a0)     = *(const float4*)(v0p);
            *(float4*)(a0 + 4) = *(const float4*)(v0p + 4);
            *(float4*)(a1)     = *(const float4*)(v1p);
            *(float4*)(a1 + 4) = *(const float4*)(v1p + 4);
            #pragma unroll
            for (int d = 0; d < 8; d++) {
                uint32_t hi, lo;
                cvt_pair(a0[d], a1[d], hi, lo);
                uint32_t off = (uint32_t)(d0 + d) * RSTR + (uint32_t)j0 * 2;
                *(uint32_t*)(sm + VH_OFF + off) = hi;
                *(uint32_t*)(sm + VL_OFF + off) = lo;
            }
        }
        __syncthreads();   // bf16 bufs ready

        // ---- prefetch next tile into the other stage (overlaps compute)
        if (it + 1 < SEQ / 64) {
            const int ktn = (it + 1) * 64;
            char* nK = sm + STG0 + ((it + 1) & 1) * 2 * STG_BYTES;
            char* nV = nK + STG_BYTES;
            #pragma unroll
            for (int p = 0; p < 4; p++) {
                int chunk = tid + p * 256;
                int r = chunk >> 4, c4 = (chunk & 15) * 4;
                CP16(smem_u32(nK + (uint32_t)(r * SSTG + c4) * 4), Kg + (size_t)(ktn + r) * HDIM + c4);
                CP16(smem_u32(nV + (uint32_t)(r * SSTG + c4) * 4), Vg + (size_t)(ktn + r) * HDIM + c4);
            }
            CP_COMMIT();
        }

        // ---- S = Q @ K^T (3-term)
        float s[8][4];
        #pragma unroll
        for (int j = 0; j < 8; j++) {
            s[j][0] = s[j][1] = s[j][2] = s[j][3] = 0.0f;
            uint32_t rowb = (uint32_t)(8 * j + (l & 7)) * RSTR + (uint32_t)(((l >> 3) & 1) * 8) * 2;
            #pragma unroll
            for (int kk = 0; kk < 4; kk++) {
                uint32_t bh[2], bl[2];
                LDSM_X2(bh[0], bh[1], smem_u32(sm + KH_OFF + rowb + kk * 32));
                LDSM_X2(bl[0], bl[1], smem_u32(sm + KL_OFF + rowb + kk * 32));
                MMA16816(s[j], qh[kk], bh);
                MMA16816(s[j], qh[kk], bl);
                MMA16816(s[j], ql[kk], bh);
            }
        }

        // ---- online softmax (log2 domain, ex2)
        float rm0 = m0r, rm1 = m1r;
        #pragma unroll
        for (int j = 0; j < 8; j++) {
            rm0 = fmaxf(rm0, fmaxf(s[j][0], s[j][1]));
            rm1 = fmaxf(rm1, fmaxf(s[j][2], s[j][3]));
        }
        rm0 = fmaxf(rm0, __shfl_xor_sync(0xffffffffu, rm0, 1));
        rm0 = fmaxf(rm0, __shfl_xor_sync(0xffffffffu, rm0, 2));
        rm1 = fmaxf(rm1, __shfl_xor_sync(0xffffffffu, rm1, 1));
        rm1 = fmaxf(rm1, __shfl_xor_sync(0xffffffffu, rm1, 2));
        float c0f = ex2(m0r - rm0), c1f = ex2(m1r - rm1);
        m0r = rm0;  m1r = rm1;
        float ls0 = 0.0f, ls1 = 0.0f;
        #pragma unroll
        for (int j = 0; j < 8; j++) {
            s[j][0] = ex2(s[j][0] - rm0);
            s[j][1] = ex2(s[j][1] - rm0);
            s[j][2] = ex2(s[j][2] - rm1);
            s[j][3] = ex2(s[j][3] - rm1);
            ls0 += s[j][0] + s[j][1];
            ls1 += s[j][2] + s[j][3];
            o[j][0] *= c0f;  o[j][1] *= c0f;
            o[j][2] *= c1f;  o[j][3] *= c1f;
        }
        ls0 += __shfl_xor_sync(0xffffffffu, ls0, 1);
        ls0 += __shfl_xor_sync(0xffffffffu, ls0, 2);
        ls1 += __shfl_xor_sync(0xffffffffu, ls1, 1);
        ls1 += __shfl_xor_sync(0xffffffffu, ls1, 2);
        l0r = l0r * c0f + ls0;
        l1r = l1r * c1f + ls1;

        // ---- O += P @ V (3-term)
        #pragma unroll
        for (int kk = 0; kk < 4; kk++) {
            uint32_t ah[4], al[4];
            cvt_pair(s[2 * kk][0],     s[2 * kk][1],     ah[0], al[0]);
            cvt_pair(s[2 * kk][2],     s[2 * kk][3],     ah[1], al[1]);
            cvt_pair(s[2 * kk + 1][0], s[2 * kk + 1][1], ah[2], al[2]);
            cvt_pair(s[2 * kk + 1][2], s[2 * kk + 1][3], ah[3], al[3]);
            #pragma unroll
            for (int j = 0; j < 8; j++) {
                uint32_t rowb = (uint32_t)(8 * j + (l & 7)) * RSTR + (uint32_t)(kk * 16 + ((l >> 3) & 1) * 8) * 2;
                uint32_t vh[2], vl[2];
                LDSM_X2(vh[0], vh[1], smem_u32(sm + VH_OFF + rowb));
                LDSM_X2(vl[0], vl[1], smem_u32(sm + VL_OFF + rowb));
                MMA16816(o[j], ah, vh);
                MMA16816(o[j], ah, vl);
                MMA16816(o[j], al, vh);
            }
        }
    }

    // ---- epilogue
    {
        float inv0 = 1.0f / l0r, inv1 = 1.0f / l1r;
        int r0 = q0 + 16 * w + (l >> 2);
        int col = 2 * (l & 3);
        float* op0 = out + ((size_t)b * SEQ + r0) * HDIM;
        float* op1 = op0 + 8 * HDIM;
        #pragma unroll
        for (int j = 0; j < 8; j++) {
            float2 v0 = {o[j][0] * inv0, o[j][1] * inv0};
            float2 v1 = {o[j][2] * inv1, o[j][3] * inv1};
            *(float2*)(op0 + 8 * j + col) = v0;
            *(float2*)(op1 + 8 * j + col) = v1;
        }
    }
}

// ---------------------------------------------------------------------------
extern "C" void kernel_launch(void* const* d_in, const int* in_sizes, int n_in,
                              void* d_out, int out_size)
{
    const float* x  = (const float*)d_in[0];
    const float* wq = (const float*)d_in[1];
    const float* wk = (const float*)d_in[2];
    const float* wv = (const float*)d_in[3];
    float* out = (float*)d_out;

    qkv_kernel<<<(BATCH * SEQ) / 128, 256>>>(x, wq, wk, wv);

    cudaFuncSetAttribute(attn_kernel, cudaFuncAttributeMaxDynamicSharedMemorySize, ATTN_SM);
    attn_kernel<<<dim3(SEQ / 128, BATCH), 256, ATTN_SM>>>(out);
}

// round 9
// speedup vs baseline: 1.5434x; 1.1747x over previous
#include <cuda_runtime.h>
#include <cuda_bf16.h>
#include <math.h>
#include <stdint.h>

#define BATCH 4
#define SEQ   4096
#define DIM   1024
#define HDIM  64

// bf16 hi/lo split Q,K,V (Q pre-scaled by 0.125*log2e). 2MB each.
__device__ __nv_bfloat16 g_Qh[(size_t)BATCH * SEQ * HDIM];
__device__ __nv_bfloat16 g_Ql[(size_t)BATCH * SEQ * HDIM];
__device__ __nv_bfloat16 g_Kh[(size_t)BATCH * SEQ * HDIM];
__device__ __nv_bfloat16 g_Kl[(size_t)BATCH * SEQ * HDIM];
__device__ __nv_bfloat16 g_Vh[(size_t)BATCH * SEQ * HDIM];
__device__ __nv_bfloat16 g_Vl[(size_t)BATCH * SEQ * HDIM];

// ===================== helpers =====================
__device__ __forceinline__ uint32_t smem_u32(const void* p) {
    uint32_t a;
    asm("{ .reg .u64 t; cvta.to.shared.u64 t, %1; cvt.u32.u64 %0, t; }" : "=r"(a) : "l"(p));
    return a;
}
__device__ __forceinline__ float ex2(float x) {
    float y; asm("ex2.approx.f32 %0, %1;" : "=f"(y) : "f"(x)); return y;
}
__device__ __forceinline__ void cvt_pair(float a, float b, uint32_t& hi, uint32_t& lo) {
    __nv_bfloat16 ah = __float2bfloat16(a);
    __nv_bfloat16 bh = __float2bfloat16(b);
    float ar = a - __bfloat162float(ah);
    float br = b - __bfloat162float(bh);
    __nv_bfloat162 H = __halves2bfloat162(ah, bh);
    __nv_bfloat162 L = __halves2bfloat162(__float2bfloat16(ar), __float2bfloat16(br));
    hi = *reinterpret_cast<uint32_t*>(&H);
    lo = *reinterpret_cast<uint32_t*>(&L);
}

#define LDSM_X4(r0, r1, r2, r3, addr) \
    asm volatile("ldmatrix.sync.aligned.m8n8.x4.shared.b16 {%0,%1,%2,%3}, [%4];" \
        : "=r"(r0), "=r"(r1), "=r"(r2), "=r"(r3) : "r"(addr))
#define LDSM_X2(r0, r1, addr) \
    asm volatile("ldmatrix.sync.aligned.m8n8.x2.shared.b16 {%0,%1}, [%2];" \
        : "=r"(r0), "=r"(r1) : "r"(addr))
#define LDSM_X2_T(r0, r1, addr) \
    asm volatile("ldmatrix.sync.aligned.m8n8.x2.trans.shared.b16 {%0,%1}, [%2];" \
        : "=r"(r0), "=r"(r1) : "r"(addr))
#define MMA16816(d, a, b) \
    asm volatile("mma.sync.aligned.m16n8k16.row.col.f32.bf16.bf16.f32 " \
        "{%0,%1,%2,%3}, {%4,%5,%6,%7}, {%8,%9}, {%0,%1,%2,%3};" \
        : "+f"((d)[0]), "+f"((d)[1]), "+f"((d)[2]), "+f"((d)[3]) \
        : "r"((a)[0]), "r"((a)[1]), "r"((a)[2]), "r"((a)[3]), "r"((b)[0]), "r"((b)[1]))
#define CP16(dst, src) \
    asm volatile("cp.async.cg.shared.global [%0], [%1], 16;" :: "r"(dst), "l"(src) : "memory")
#define CP_COMMIT() asm volatile("cp.async.commit_group;" ::: "memory")
#define CP_WAIT0()  asm volatile("cp.async.wait_group 0;" ::: "memory")

// ---------------------------------------------------------------------------
// QKV via tensor cores; epilogue writes bf16 hi/lo split (Q scaled).
// Fused N=192, M-tile 128, K-chunk 16. grid = 128, block 256.
// ---------------------------------------------------------------------------
#define XSTR 24
__global__ __launch_bounds__(256, 1) void qkv_kernel(
    const float* __restrict__ x, const float* __restrict__ wq,
    const float* __restrict__ wk, const float* __restrict__ wv)
{
    __shared__ __align__(16) __nv_bfloat16 XH[128 * XSTR], XL[128 * XSTR];
    __shared__ __align__(16) __nv_bfloat16 WH[192 * XSTR], WL[192 * XSTR];

    const int tid = threadIdx.x;
    const int w = tid >> 5, l = tid & 31;
    const int m0 = blockIdx.x * 128;
    const float* Wp[3] = {wq, wk, wv};

    float acc[24][4];
    #pragma unroll
    for (int j = 0; j < 24; j++) { acc[j][0] = acc[j][1] = acc[j][2] = acc[j][3] = 0.0f; }

    for (int it = 0; it < DIM / 16; it++) {
        const int k0 = it * 16;
        {
            int r = tid >> 1, c = (tid & 1) * 8;
            const float* xp = x + (size_t)(m0 + r) * DIM + k0 + c;
            float4 v0 = *(const float4*)(xp);
            float4 v1 = *(const float4*)(xp + 4);
            uint32_t h, lo;
            uint32_t base = (uint32_t)r * XSTR + c;
            cvt_pair(v0.x, v0.y, h, lo);
            *(uint32_t*)(XH + base)     = h;  *(uint32_t*)(XL + base)     = lo;
            cvt_pair(v0.z, v0.w, h, lo);
            *(uint32_t*)(XH + base + 2) = h;  *(uint32_t*)(XL + base + 2) = lo;
            cvt_pair(v1.x, v1.y, h, lo);
            *(uint32_t*)(XH + base + 4) = h;  *(uint32_t*)(XL + base + 4) = lo;
            cvt_pair(v1.z, v1.w, h, lo);
            *(uint32_t*)(XH + base + 6) = h;  *(uint32_t*)(XL + base + 6) = lo;
        }
        #pragma unroll
        for (int p = 0; p < 3; p++) {
            int n = p * 64 + (tid >> 2), c = (tid & 3) * 4;
            const float* wp = Wp[p] + (size_t)(n - p * 64) * DIM + k0 + c;
            float4 v = *(const float4*)(wp);
            uint32_t h, lo;
            uint32_t base = (uint32_t)n * XSTR + c;
            cvt_pair(v.x, v.y, h, lo);
            *(uint32_t*)(WH + base)     = h;  *(uint32_t*)(WL + base)     = lo;
            cvt_pair(v.z, v.w, h, lo);
            *(uint32_t*)(WH + base + 2) = h;  *(uint32_t*)(WL + base + 2) = lo;
        }
        __syncthreads();

        uint32_t ah[4], al[4];
        uint32_t arow = ((uint32_t)(16 * w + (l & 15)) * XSTR + (uint32_t)((l >> 4) * 8)) * 2;
        LDSM_X4(ah[0], ah[1], ah[2], ah[3], smem_u32((const char*)XH + arow));
        LDSM_X4(al[0], al[1], al[2], al[3], smem_u32((const char*)XL + arow));
        #pragma unroll
        for (int j = 0; j < 24; j++) {
            uint32_t brow = ((uint32_t)(8 * j + (l & 7)) * XSTR + (uint32_t)(((l >> 3) & 1) * 8)) * 2;
            uint32_t bh[2], bl[2];
            LDSM_X2(bh[0], bh[1], smem_u32((const char*)WH + brow));
            LDSM_X2(bl[0], bl[1], smem_u32((const char*)WL + brow));
            MMA16816(acc[j], ah, bh);
            MMA16816(acc[j], ah, bl);
            MMA16816(acc[j], al, bh);
        }
        __syncthreads();
    }

    // epilogue: split to bf16 hi/lo, Q scaled by 0.125*log2(e)
    {
        const float QS = 0.125f * 1.4426950408889634f;
        __nv_bfloat16* const AH[3] = {g_Qh, g_Kh, g_Vh};
        __nv_bfloat16* const AL[3] = {g_Ql, g_Kl, g_Vl};
        int r0 = m0 + 16 * w + (l >> 2);
        int col2 = 2 * (l & 3);
        #pragma unroll
        for (int j = 0; j < 24; j++) {
            int mat = j >> 3;
            int col = 8 * (j & 7) + col2;
            float sc = (mat == 0) ? QS : 1.0f;
            uint32_t h, lo;
            cvt_pair(acc[j][0] * sc, acc[j][1] * sc, h, lo);
            *(uint32_t*)(AH[mat] + (size_t)r0 * HDIM + col) = h;
            *(uint32_t*)(AL[mat] + (size_t)r0 * HDIM + col) = lo;
            cvt_pair(acc[j][2] * sc, acc[j][3] * sc, h, lo);
            *(uint32_t*)(AH[mat] + (size_t)(r0 + 8) * HDIM + col) = h;
            *(uint32_t*)(AL[mat] + (size_t)(r0 + 8) * HDIM + col) = lo;
        }
    }
}

// ---------------------------------------------------------------------------
// FA2 attention: zero in-loop conversion. cp.async bf16 tiles (double buffer),
// K [key][hd] for S (non-trans ldmatrix), V [key][hd] for PV (trans ldmatrix).
// 256 threads = 8 warps x 16 q-rows, KV tile 64. grid = (SEQ/128, BATCH).
// ---------------------------------------------------------------------------
#define RSTR   144
#define STG_B  36864   // per stage: KH +0, KL +9216, VH +18432, VL +27648
#define ATTN_SM (2 * STG_B)   // 73728

__global__ __launch_bounds__(256, 1) void attn_kernel(float* __restrict__ out)
{
    extern __shared__ __align__(16) char sm[];

    const int tid = threadIdx.x;
    const int w = tid >> 5, l = tid & 31;
    const int b = blockIdx.y;
    const int q0 = blockIdx.x * 128;
    const size_t boff = (size_t)b * SEQ * HDIM;

    const __nv_bfloat16* Khp = g_Kh + boff;
    const __nv_bfloat16* Klp = g_Kl + boff;
    const __nv_bfloat16* Vhp = g_Vh + boff;
    const __nv_bfloat16* Vlp = g_Vl + boff;

    // ---- prologue: stage KV tile 0 into stage0, Q tile into stage1
    #pragma unroll
    for (int p = 0; p < 8; p++) {                 // arr = p>>1: KH,KL,VH,VL
        int wi = (p & 1) * 256 + tid;
        int r = wi >> 3, c = wi & 7;
        const __nv_bfloat16* src =
            (p < 2) ? Khp : (p < 4) ? Klp : (p < 6) ? Vhp : Vlp;
        CP16(smem_u32(sm + (p >> 1) * 9216 + r * RSTR + c * 16),
             src + (size_t)r * HDIM + c * 8);
    }
    CP_COMMIT();
    #pragma unroll
    for (int p = 0; p < 8; p++) {                 // arr = p>>2: Qh, Ql
        int wi = (p & 3) * 256 + tid;
        int r = wi >> 3, c = wi & 7;
        const __nv_bfloat16* src = ((p < 4) ? g_Qh : g_Ql) + boff;
        CP16(smem_u32(sm + STG_B + (p >> 2) * 18432 + r * RSTR + c * 16),
             src + (size_t)(q0 + r) * HDIM + c * 8);
    }
    CP_COMMIT();
    CP_WAIT0();
    __syncthreads();

    // ---- Q fragments (held in regs; stage1 freed after this + next sync)
    uint32_t qh[4][4], ql[4][4];
    {
        uint32_t rowb = (uint32_t)(16 * w + (l & 15)) * RSTR + (uint32_t)(l >> 4) * 16;
        #pragma unroll
        for (int kk = 0; kk < 4; kk++) {
            LDSM_X4(qh[kk][0], qh[kk][1], qh[kk][2], qh[kk][3], smem_u32(sm + STG_B + rowb + kk * 32));
            LDSM_X4(ql[kk][0], ql[kk][1], ql[kk][2], ql[kk][3], smem_u32(sm + STG_B + 18432 + rowb + kk * 32));
        }
    }

    float o[8][4];
    #pragma unroll
    for (int j = 0; j < 8; j++) { o[j][0] = o[j][1] = o[j][2] = o[j][3] = 0.0f; }
    float m0r = -1e30f, m1r = -1e30f, l0r = 0.0f, l1r = 0.0f;

    for (int it = 0; it < SEQ / 64; it++) {
        const char* base = sm + (it & 1) * STG_B;

        CP_WAIT0();        // current stage landed (it=0: already waited)
        __syncthreads();   // visible to all; prev iter's reads of next stage done

        // ---- prefetch next tile (overlaps all compute below)
        if (it + 1 < SEQ / 64) {
            const int ktn = (it + 1) * 64;
            char* nb = sm + ((it + 1) & 1) * STG_B;
            #pragma unroll
            for (int p = 0; p < 8; p++) {
                int wi = (p & 1) * 256 + tid;
                int r = wi >> 3, c = wi & 7;
                const __nv_bfloat16* src =
                    (p < 2) ? Khp : (p < 4) ? Klp : (p < 6) ? Vhp : Vlp;
                CP16(smem_u32(nb + (p >> 1) * 9216 + r * RSTR + c * 16),
                     src + (size_t)(ktn + r) * HDIM + c * 8);
            }
            CP_COMMIT();
        }

        // ---- S = Q @ K^T (3-term)
        float s[8][4];
        #pragma unroll
        for (int j = 0; j < 8; j++) {
            s[j][0] = s[j][1] = s[j][2] = s[j][3] = 0.0f;
            uint32_t rowb = (uint32_t)(8 * j + (l & 7)) * RSTR + (uint32_t)(((l >> 3) & 1) * 8) * 2;
            #pragma unroll
            for (int kk = 0; kk < 4; kk++) {
                uint32_t bh[2], bl[2];
                LDSM_X2(bh[0], bh[1], smem_u32(base + rowb + kk * 32));
                LDSM_X2(bl[0], bl[1], smem_u32(base + 9216 + rowb + kk * 32));
                MMA16816(s[j], qh[kk], bh);
                MMA16816(s[j], qh[kk], bl);
                MMA16816(s[j], ql[kk], bh);
            }
        }

        // ---- online softmax (log2 domain)
        float rm0 = m0r, rm1 = m1r;
        #pragma unroll
        for (int j = 0; j < 8; j++) {
            rm0 = fmaxf(rm0, fmaxf(s[j][0], s[j][1]));
            rm1 = fmaxf(rm1, fmaxf(s[j][2], s[j][3]));
        }
        rm0 = fmaxf(rm0, __shfl_xor_sync(0xffffffffu, rm0, 1));
        rm0 = fmaxf(rm0, __shfl_xor_sync(0xffffffffu, rm0, 2));
        rm1 = fmaxf(rm1, __shfl_xor_sync(0xffffffffu, rm1, 1));
        rm1 = fmaxf(rm1, __shfl_xor_sync(0xffffffffu, rm1, 2));
        float c0f = ex2(m0r - rm0), c1f = ex2(m1r - rm1);
        m0r = rm0;  m1r = rm1;
        float ls0 = 0.0f, ls1 = 0.0f;
        #pragma unroll
        for (int j = 0; j < 8; j++) {
            s[j][0] = ex2(s[j][0] - rm0);
            s[j][1] = ex2(s[j][1] - rm0);
            s[j][2] = ex2(s[j][2] - rm1);
            s[j][3] = ex2(s[j][3] - rm1);
            ls0 += s[j][0] + s[j][1];
            ls1 += s[j][2] + s[j][3];
            o[j][0] *= c0f;  o[j][1] *= c0f;
            o[j][2] *= c1f;  o[j][3] *= c1f;
        }
        ls0 += __shfl_xor_sync(0xffffffffu, ls0, 1);
        ls0 += __shfl_xor_sync(0xffffffffu, ls0, 2);
        ls1 += __shfl_xor_sync(0xffffffffu, ls1, 1);
        ls1 += __shfl_xor_sync(0xffffffffu, ls1, 2);
        l0r = l0r * c0f + ls0;
        l1r = l1r * c1f + ls1;

        // ---- O += P @ V (3-term; V via trans ldmatrix from [key][hd])
        #pragma unroll
        for (int kk = 0; kk < 4; kk++) {
            uint32_t ah[4], al[4];
            cvt_pair(s[2 * kk][0],     s[2 * kk][1],     ah[0], al[0]);
            cvt_pair(s[2 * kk][2],     s[2 * kk][3],     ah[1], al[1]);
            cvt_pair(s[2 * kk + 1][0], s[2 * kk + 1][1], ah[2], al[2]);
            cvt_pair(s[2 * kk + 1][2], s[2 * kk + 1][3], ah[3], al[3]);
            uint32_t vrow = (uint32_t)(16 * kk + (l & 7) + 8 * ((l >> 3) & 1)) * RSTR;
            #pragma unroll
            for (int j = 0; j < 8; j++) {
                uint32_t off = vrow + (uint32_t)j * 16;
                uint32_t vh[2], vl[2];
                LDSM_X2_T(vh[0], vh[1], smem_u32(base + 18432 + off));
                LDSM_X2_T(vl[0], vl[1], smem_u32(base + 27648 + off));
                MMA16816(o[j], ah, vh);
                MMA16816(o[j], ah, vl);
                MMA16816(o[j], al, vh);
            }
        }
    }

    // ---- epilogue
    {
        float inv0 = 1.0f / l0r, inv1 = 1.0f / l1r;
        int r0 = q0 + 16 * w + (l >> 2);
        int col = 2 * (l & 3);
        float* op0 = out + ((size_t)b * SEQ + r0) * HDIM;
        float* op1 = op0 + 8 * HDIM;
        #pragma unroll
        for (int j = 0; j < 8; j++) {
            float2 v0 = {o[j][0] * inv0, o[j][1] * inv0};
            float2 v1 = {o[j][2] * inv1, o[j][3] * inv1};
            *(float2*)(op0 + 8 * j + col) = v0;
            *(float2*)(op1 + 8 * j + col) = v1;
        }
    }
}

// ---------------------------------------------------------------------------
extern "C" void kernel_launch(void* const* d_in, const int* in_sizes, int n_in,
                              void* d_out, int out_size)
{
    const float* x  = (const float*)d_in[0];
    const float* wq = (const float*)d_in[1];
    const float* wk = (const float*)d_in[2];
    const float* wv = (const float*)d_in[3];
    float* out = (float*)d_out;

    qkv_kernel<<<(BATCH * SEQ) / 128, 256>>>(x, wq, wk, wv);

    cudaFuncSetAttribute(attn_kernel, cudaFuncAttributeMaxDynamicSharedMemorySize, ATTN_SM);
    attn_kernel<<<dim3(SEQ / 128, BATCH), 256, ATTN_SM>>>(out);
}

// round 10
// speedup vs baseline: 1.6022x; 1.0381x over previous
#include <cuda_runtime.h>
#include <cuda_bf16.h>
#include <math.h>
#include <stdint.h>

#define BATCH 4
#define SEQ   4096
#define DIM   1024
#define HDIM  64

// bf16 hi/lo split Q,K,V (Q pre-scaled by 0.125*log2e). 2MB each.
__device__ __nv_bfloat16 g_Qh[(size_t)BATCH * SEQ * HDIM];
__device__ __nv_bfloat16 g_Ql[(size_t)BATCH * SEQ * HDIM];
__device__ __nv_bfloat16 g_Kh[(size_t)BATCH * SEQ * HDIM];
__device__ __nv_bfloat16 g_Kl[(size_t)BATCH * SEQ * HDIM];
__device__ __nv_bfloat16 g_Vh[(size_t)BATCH * SEQ * HDIM];
__device__ __nv_bfloat16 g_Vl[(size_t)BATCH * SEQ * HDIM];
// bf16 hi/lo split weights, [192][1024] (rows: 0-63 wq, 64-127 wk, 128-191 wv)
__device__ __nv_bfloat16 g_Wh[192 * DIM];
__device__ __nv_bfloat16 g_Wl[192 * DIM];

// ===================== helpers =====================
__device__ __forceinline__ uint32_t smem_u32(const void* p) {
    uint32_t a;
    asm("{ .reg .u64 t; cvta.to.shared.u64 t, %1; cvt.u32.u64 %0, t; }" : "=r"(a) : "l"(p));
    return a;
}
__device__ __forceinline__ float ex2(float x) {
    float y; asm("ex2.approx.f32 %0, %1;" : "=f"(y) : "f"(x)); return y;
}
__device__ __forceinline__ void cvt_pair(float a, float b, uint32_t& hi, uint32_t& lo) {
    __nv_bfloat16 ah = __float2bfloat16(a);
    __nv_bfloat16 bh = __float2bfloat16(b);
    float ar = a - __bfloat162float(ah);
    float br = b - __bfloat162float(bh);
    __nv_bfloat162 H = __halves2bfloat162(ah, bh);
    __nv_bfloat162 L = __halves2bfloat162(__float2bfloat16(ar), __float2bfloat16(br));
    hi = *reinterpret_cast<uint32_t*>(&H);
    lo = *reinterpret_cast<uint32_t*>(&L);
}

#define LDSM_X4(r0, r1, r2, r3, addr) \
    asm volatile("ldmatrix.sync.aligned.m8n8.x4.shared.b16 {%0,%1,%2,%3}, [%4];" \
        : "=r"(r0), "=r"(r1), "=r"(r2), "=r"(r3) : "r"(addr))
#define LDSM_X2(r0, r1, addr) \
    asm volatile("ldmatrix.sync.aligned.m8n8.x2.shared.b16 {%0,%1}, [%2];" \
        : "=r"(r0), "=r"(r1) : "r"(addr))
#define LDSM_X2_T(r0, r1, addr) \
    asm volatile("ldmatrix.sync.aligned.m8n8.x2.trans.shared.b16 {%0,%1}, [%2];" \
        : "=r"(r0), "=r"(r1) : "r"(addr))
#define MMA16816(d, a, b) \
    asm volatile("mma.sync.aligned.m16n8k16.row.col.f32.bf16.bf16.f32 " \
        "{%0,%1,%2,%3}, {%4,%5,%6,%7}, {%8,%9}, {%0,%1,%2,%3};" \
        : "+f"((d)[0]), "+f"((d)[1]), "+f"((d)[2]), "+f"((d)[3]) \
        : "r"((a)[0]), "r"((a)[1]), "r"((a)[2]), "r"((a)[3]), "r"((b)[0]), "r"((b)[1]))
#define CP16(dst, src) \
    asm volatile("cp.async.cg.shared.global [%0], [%1], 16;" :: "r"(dst), "l"(src) : "memory")
#define CP_COMMIT() asm volatile("cp.async.commit_group;" ::: "memory")
#define CP_WAIT0()  asm volatile("cp.async.wait_group 0;" ::: "memory")

// ---------------------------------------------------------------------------
// Prepass: split weights into bf16 hi/lo. grid (64, 3), block 256.
// ---------------------------------------------------------------------------
__global__ void convert_w(const float* __restrict__ wq, const float* __restrict__ wk,
                          const float* __restrict__ wv)
{
    int mat = blockIdx.y;
    const float* src = (mat == 0) ? wq : (mat == 1) ? wk : wv;
    int idx = (blockIdx.x * 256 + threadIdx.x) * 4;   // within 64*1024 matrix
    float4 v = *(const float4*)(src + idx);
    uint32_t h0, l0, h1, l1;
    cvt_pair(v.x, v.y, h0, l0);
    cvt_pair(v.z, v.w, h1, l1);
    size_t o = (size_t)mat * (64 * DIM) + idx;
    *(uint32_t*)(g_Wh + o)     = h0;  *(uint32_t*)(g_Wh + o + 2) = h1;
    *(uint32_t*)(g_Wl + o)     = l0;  *(uint32_t*)(g_Wl + o + 2) = l1;
}

// ---------------------------------------------------------------------------
// QKV GEMM: fused N=192, M-tile 128, K-chunk 16, double-buffered.
// W streams as pre-split bf16 via cp.async; X loads fp32->regs, converts, STS.
// Per stage: XH@0(6144) XL@6144 WH@12288(9216) WL@21504. Stage=30720.
// grid = 128, block 256. Epilogue writes bf16 hi/lo split of Q,K,V.
// ---------------------------------------------------------------------------
#define QSTG 30720
#define QKV_SM (2 * QSTG)
__global__ __launch_bounds__(256, 1) void qkv_kernel(const float* __restrict__ x)
{
    extern __shared__ __align__(16) char smq[];

    const int tid = threadIdx.x;
    const int w = tid >> 5, l = tid & 31;
    const int m0 = blockIdx.x * 128;

    // X ownership: row r = tid>>1, 8 floats at (tid&1)*8
    const float* xrow = x + (size_t)(m0 + (tid >> 1)) * DIM + (tid & 1) * 8;
    const uint32_t xdst = (uint32_t)(tid >> 1) * 48 + (uint32_t)(tid & 1) * 16;

    float acc[24][4];
    #pragma unroll
    for (int j = 0; j < 24; j++) { acc[j][0] = acc[j][1] = acc[j][2] = acc[j][3] = 0.0f; }

    // ---- prologue: chunk 0 (W cp.async + X ldg/convert/STS into stage 0)
    {
        #pragma unroll
        for (int p = 0; p < 3; p++) {
            int wi = p * 256 + tid;               // 0..767
            int arr = (wi >= 384) ? 1 : 0;
            int i = wi - 384 * arr;
            int r = i >> 1, c = i & 1;
            const __nv_bfloat16* src = (arr ? g_Wl : g_Wh) + (size_t)r * DIM + c * 8;
            CP16(smem_u32(smq + 12288 + arr * 9216 + r * 48 + c * 16), src);
        }
        float4 xa = *(const float4*)(xrow);
        float4 xb = *(const float4*)(xrow + 4);
        uint32_t h[4], lo[4];
        cvt_pair(xa.x, xa.y, h[0], lo[0]);  cvt_pair(xa.z, xa.w, h[1], lo[1]);
        cvt_pair(xb.x, xb.y, h[2], lo[2]);  cvt_pair(xb.z, xb.w, h[3], lo[3]);
        *(uint4*)(smq + xdst)        = make_uint4(h[0], h[1], h[2], h[3]);
        *(uint4*)(smq + 6144 + xdst) = make_uint4(lo[0], lo[1], lo[2], lo[3]);
        CP_COMMIT();
    }

    for (int it = 0; it < DIM / 16; it++) {
        char* base = smq + (it & 1) * QSTG;
        char* nxt  = smq + ((it + 1) & 1) * QSTG;
        CP_WAIT0();
        __syncthreads();

        float4 xa, xb;
        const bool more = (it + 1 < DIM / 16);
        if (more) {
            const int k0n = (it + 1) * 16;
            // W chunk it+1 -> next stage (async)
            #pragma unroll
            for (int p = 0; p < 3; p++) {
                int wi = p * 256 + tid;
                int arr = (wi >= 384) ? 1 : 0;
                int i = wi - 384 * arr;
                int r = i >> 1, c = i & 1;
                const __nv_bfloat16* src = (arr ? g_Wl : g_Wh) + (size_t)r * DIM + k0n + c * 8;
                CP16(smem_u32(nxt + 12288 + arr * 9216 + r * 48 + c * 16), src);
            }
            // X chunk it+1 -> regs (latency hidden under compute below)
            xa = *(const float4*)(xrow + k0n);
            xb = *(const float4*)(xrow + k0n + 4);
        }

        // ---- compute chunk it
        uint32_t ah[4], al[4];
        uint32_t arow = ((uint32_t)(16 * w + (l & 15)) * 24 + (uint32_t)((l >> 4) * 8)) * 2;
        LDSM_X4(ah[0], ah[1], ah[2], ah[3], smem_u32(base + arow));
        LDSM_X4(al[0], al[1], al[2], al[3], smem_u32(base + 6144 + arow));
        #pragma unroll
        for (int j = 0; j < 24; j++) {
            uint32_t brow = ((uint32_t)(8 * j + (l & 7)) * 24 + (uint32_t)(((l >> 3) & 1) * 8)) * 2;
            uint32_t bh[2], bl[2];
            LDSM_X2(bh[0], bh[1], smem_u32(base + 12288 + brow));
            LDSM_X2(bl[0], bl[1], smem_u32(base + 21504 + brow));
            MMA16816(acc[j], ah, bh);
            MMA16816(acc[j], ah, bl);
            MMA16816(acc[j], al, bh);
        }

        if (more) {
            uint32_t h[4], lo[4];
            cvt_pair(xa.x, xa.y, h[0], lo[0]);  cvt_pair(xa.z, xa.w, h[1], lo[1]);
            cvt_pair(xb.x, xb.y, h[2], lo[2]);  cvt_pair(xb.z, xb.w, h[3], lo[3]);
            *(uint4*)(nxt + xdst)        = make_uint4(h[0], h[1], h[2], h[3]);
            *(uint4*)(nxt + 6144 + xdst) = make_uint4(lo[0], lo[1], lo[2], lo[3]);
            CP_COMMIT();
        }
    }

    // ---- epilogue: split to bf16 hi/lo, Q scaled by 0.125*log2(e)
    {
        const float QS = 0.125f * 1.4426950408889634f;
        __nv_bfloat16* const AH[3] = {g_Qh, g_Kh, g_Vh};
        __nv_bfloat16* const AL[3] = {g_Ql, g_Kl, g_Vl};
        int r0 = m0 + 16 * w + (l >> 2);
        int col2 = 2 * (l & 3);
        #pragma unroll
        for (int j = 0; j < 24; j++) {
            int mat = j >> 3;
            int col = 8 * (j & 7) + col2;
            float sc = (mat == 0) ? QS : 1.0f;
            uint32_t h, lo;
            cvt_pair(acc[j][0] * sc, acc[j][1] * sc, h, lo);
            *(uint32_t*)(AH[mat] + (size_t)r0 * HDIM + col) = h;
            *(uint32_t*)(AL[mat] + (size_t)r0 * HDIM + col) = lo;
            cvt_pair(acc[j][2] * sc, acc[j][3] * sc, h, lo);
            *(uint32_t*)(AH[mat] + (size_t)(r0 + 8) * HDIM + col) = h;
            *(uint32_t*)(AL[mat] + (size_t)(r0 + 8) * HDIM + col) = lo;
        }
    }
}

// ---------------------------------------------------------------------------
// FA2 attention: 128 threads (4 warps), q-tile 64, 2 CTAs/SM for phase overlap.
// cp.async bf16 double buffer; K non-trans ldmatrix, V trans ldmatrix.
// grid = (SEQ/64, BATCH) = 256 CTAs.
// ---------------------------------------------------------------------------
#define RSTR   144
#define STG_B  36864   // per stage: KH +0, KL +9216, VH +18432, VL +27648
#define ATTN_SM (2 * STG_B)   // 73728 -> 2 CTAs/SM

__global__ __launch_bounds__(128, 2) void attn_kernel(float* __restrict__ out)
{
    extern __shared__ __align__(16) char sm[];

    const int tid = threadIdx.x;
    const int w = tid >> 5, l = tid & 31;
    const int b = blockIdx.y;
    const int q0 = blockIdx.x * 64;
    const size_t boff = (size_t)b * SEQ * HDIM;

    const __nv_bfloat16* Khp = g_Kh + boff;
    const __nv_bfloat16* Klp = g_Kl + boff;
    const __nv_bfloat16* Vhp = g_Vh + boff;
    const __nv_bfloat16* Vlp = g_Vl + boff;

    // ---- prologue: KV tile 0 -> stage0, Q tile -> stage1
    #pragma unroll
    for (int p = 0; p < 16; p++) {
        int arr = p >> 2;                         // 0=KH 1=KL 2=VH 3=VL
        int i = (p & 3) * 128 + tid;              // 0..511
        int r = i >> 3, c = i & 7;
        const __nv_bfloat16* src =
            (arr == 0) ? Khp : (arr == 1) ? Klp : (arr == 2) ? Vhp : Vlp;
        CP16(smem_u32(sm + arr * 9216 + r * RSTR + c * 16), src + (size_t)r * HDIM + c * 8);
    }
    CP_COMMIT();
    #pragma unroll
    for (int p = 0; p < 8; p++) {                 // arr: 0=Qh 1=Ql
        int arr = p >> 2;
        int i = (p & 3) * 128 + tid;
        int r = i >> 3, c = i & 7;
        const __nv_bfloat16* src = ((arr == 0) ? g_Qh : g_Ql) + boff;
        CP16(smem_u32(sm + STG_B + arr * 9216 + r * RSTR + c * 16),
             src + (size_t)(q0 + r) * HDIM + c * 8);
    }
    CP_COMMIT();
    CP_WAIT0();
    __syncthreads();

    // ---- Q fragments (regs for whole kernel)
    uint32_t qh[4][4], ql[4][4];
    {
        uint32_t rowb = (uint32_t)(16 * w + (l & 15)) * RSTR + (uint32_t)(l >> 4) * 16;
        #pragma unroll
        for (int kk = 0; kk < 4; kk++) {
            LDSM_X4(qh[kk][0], qh[kk][1], qh[kk][2], qh[kk][3], smem_u32(sm + STG_B + rowb + kk * 32));
            LDSM_X4(ql[kk][0], ql[kk][1], ql[kk][2], ql[kk][3], smem_u32(sm + STG_B + 9216 + rowb + kk * 32));
        }
    }

    float o[8][4];
    #pragma unroll
    for (int j = 0; j < 8; j++) { o[j][0] = o[j][1] = o[j][2] = o[j][3] = 0.0f; }
    float m0r = -1e30f, m1r = -1e30f, l0r = 0.0f, l1r = 0.0f;

    for (int it = 0; it < SEQ / 64; it++) {
        const char* base = sm + (it & 1) * STG_B;

        CP_WAIT0();
        __syncthreads();

        // ---- prefetch next KV tile (overlaps compute)
        if (it + 1 < SEQ / 64) {
            const int ktn = (it + 1) * 64;
            char* nb = sm + ((it + 1) & 1) * STG_B;
            #pragma unroll
            for (int p = 0; p < 16; p++) {
                int arr = p >> 2;
                int i = (p & 3) * 128 + tid;
                int r = i >> 3, c = i & 7;
                const __nv_bfloat16* src =
                    (arr == 0) ? Khp : (arr == 1) ? Klp : (arr == 2) ? Vhp : Vlp;
                CP16(smem_u32(nb + arr * 9216 + r * RSTR + c * 16),
                     src + (size_t)(ktn + r) * HDIM + c * 8);
            }
            CP_COMMIT();
        }

        // ---- S = Q @ K^T (3-term)
        float s[8][4];
        #pragma unroll
        for (int j = 0; j < 8; j++) {
            s[j][0] = s[j][1] = s[j][2] = s[j][3] = 0.0f;
            uint32_t rowb = (uint32_t)(8 * j + (l & 7)) * RSTR + (uint32_t)(((l >> 3) & 1) * 8) * 2;
            #pragma unroll
            for (int kk = 0; kk < 4; kk++) {
                uint32_t bh[2], bl[2];
                LDSM_X2(bh[0], bh[1], smem_u32(base + rowb + kk * 32));
                LDSM_X2(bl[0], bl[1], smem_u32(base + 9216 + rowb + kk * 32));
                MMA16816(s[j], qh[kk], bh);
                MMA16816(s[j], qh[kk], bl);
                MMA16816(s[j], ql[kk], bh);
            }
        }

        // ---- online softmax (log2 domain)
        float rm0 = m0r, rm1 = m1r;
        #pragma unroll
        for (int j = 0; j < 8; j++) {
            rm0 = fmaxf(rm0, fmaxf(s[j][0], s[j][1]));
            rm1 = fmaxf(rm1, fmaxf(s[j][2], s[j][3]));
        }
        rm0 = fmaxf(rm0, __shfl_xor_sync(0xffffffffu, rm0, 1));
        rm0 = fmaxf(rm0, __shfl_xor_sync(0xffffffffu, rm0, 2));
        rm1 = fmaxf(rm1, __shfl_xor_sync(0xffffffffu, rm1, 1));
        rm1 = fmaxf(rm1, __shfl_xor_sync(0xffffffffu, rm1, 2));
        float c0f = ex2(m0r - rm0), c1f = ex2(m1r - rm1);
        m0r = rm0;  m1r = rm1;
        float ls0 = 0.0f, ls1 = 0.0f;
        #pragma unroll
        for (int j = 0; j < 8; j++) {
            s[j][0] = ex2(s[j][0] - rm0);
            s[j][1] = ex2(s[j][1] - rm0);
            s[j][2] = ex2(s[j][2] - rm1);
            s[j][3] = ex2(s[j][3] - rm1);
            ls0 += s[j][0] + s[j][1];
            ls1 += s[j][2] + s[j][3];
            o[j][0] *= c0f;  o[j][1] *= c0f;
            o[j][2] *= c1f;  o[j][3] *= c1f;
        }
        ls0 += __shfl_xor_sync(0xffffffffu, ls0, 1);
        ls0 += __shfl_xor_sync(0xffffffffu, ls0, 2);
        ls1 += __shfl_xor_sync(0xffffffffu, ls1, 1);
        ls1 += __shfl_xor_sync(0xffffffffu, ls1, 2);
        l0r = l0r * c0f + ls0;
        l1r = l1r * c1f + ls1;

        // ---- O += P @ V (3-term; V via trans ldmatrix)
        #pragma unroll
        for (int kk = 0; kk < 4; kk++) {
            uint32_t ah[4], al[4];
            cvt_pair(s[2 * kk][0],     s[2 * kk][1],     ah[0], al[0]);
            cvt_pair(s[2 * kk][2],     s[2 * kk][3],     ah[1], al[1]);
            cvt_pair(s[2 * kk + 1][0], s[2 * kk + 1][1], ah[2], al[2]);
            cvt_pair(s[2 * kk + 1][2], s[2 * kk + 1][3], ah[3], al[3]);
            uint32_t vrow = (uint32_t)(16 * kk + (l & 7) + 8 * ((l >> 3) & 1)) * RSTR;
            #pragma unroll
            for (int j = 0; j < 8; j++) {
                uint32_t off = vrow + (uint32_t)j * 16;
                uint32_t vh[2], vl[2];
                LDSM_X2_T(vh[0], vh[1], smem_u32(base + 18432 + off));
                LDSM_X2_T(vl[0], vl[1], smem_u32(base + 27648 + off));
                MMA16816(o[j], ah, vh);
                MMA16816(o[j], ah, vl);
                MMA16816(o[j], al, vh);
            }
        }
    }

    // ---- epilogue
    {
        float inv0 = 1.0f / l0r, inv1 = 1.0f / l1r;
        int r0 = q0 + 16 * w + (l >> 2);
        int col = 2 * (l & 3);
        float* op0 = out + ((size_t)b * SEQ + r0) * HDIM;
        float* op1 = op0 + 8 * HDIM;
        #pragma unroll
        for (int j = 0; j < 8; j++) {
            float2 v0 = {o[j][0] * inv0, o[j][1] * inv0};
            float2 v1 = {o[j][2] * inv1, o[j][3] * inv1};
            *(float2*)(op0 + 8 * j + col) = v0;
            *(float2*)(op1 + 8 * j + col) = v1;
        }
    }
}

// ---------------------------------------------------------------------------
extern "C" void kernel_launch(void* const* d_in, const int* in_sizes, int n_in,
                              void* d_out, int out_size)
{
    const float* x  = (const float*)d_in[0];
    const float* wq = (const float*)d_in[1];
    const float* wk = (const float*)d_in[2];
    const float* wv = (const float*)d_in[3];
    float* out = (float*)d_out;

    convert_w<<<dim3(64, 3), 256>>>(wq, wk, wv);

    cudaFuncSetAttribute(qkv_kernel, cudaFuncAttributeMaxDynamicSharedMemorySize, QKV_SM);
    qkv_kernel<<<(BATCH * SEQ) / 128, 256, QKV_SM>>>(x);

    cudaFuncSetAttribute(attn_kernel, cudaFuncAttributeMaxDynamicSharedMemorySize, ATTN_SM);
    attn_kernel<<<dim3(SEQ / 64, BATCH), 128, ATTN_SM>>>(out);
}